// round 2
// baseline (speedup 1.0000x reference)
#include <cuda_runtime.h>
#include <math.h>

// Problem dims
#define BB 8
#define CI 64
#define CO 128
#define HH 256
#define WW 256

// Output offsets (ll, m_ll, lh, hl, hh, m_lh, m_hl, m_hh)
#define SUB (BB*CO*128*128)      // 16777216
#define MSK (BB*128*128)         // 131072
#define OFF_LL  0
#define OFF_MLL (SUB)
#define OFF_LH  (SUB + MSK)
#define OFF_HL  (2*SUB + MSK)
#define OFF_HH  (3*SUB + MSK)
#define OFF_MLH (4*SUB + MSK)
#define OFF_MHL (4*SUB + 2*MSK)
#define OFF_MHH (4*SUB + 3*MSK)

typedef unsigned long long ull;

// Scratch
__device__ float g_x[(size_t)BB*CO*HH*WW];     // conv out, then GDN in-place
__device__ float g_ratio[BB*HH*WW];            // >0 <=> valid
__device__ float g_inv_sigma;

__constant__ float c_h0[9] = {
    0.026748757410810f, -0.016864118442875f, -0.078223266528990f,
    0.266864118442875f,  0.602949018236360f,  0.266864118442875f,
   -0.078223266528990f, -0.016864118442875f,  0.026748757410810f};
__constant__ float c_h1[7] = {
    0.091271763114250f, -0.057543526228500f, -0.591271763114250f,
    1.115087052457000f, -0.591271763114250f, -0.057543526228500f,
    0.091271763114250f};

__device__ __forceinline__ int refl(int i, int n) {
    return i < 0 ? -i : (i >= n ? 2*n - 2 - i : i);
}

// f32x2 packed helpers (sm_100+)
__device__ __forceinline__ ull pk(float a, float b) {
    ull r; asm("mov.b64 %0, {%1, %2};" : "=l"(r) : "f"(a), "f"(b)); return r;
}
__device__ __forceinline__ void upk(ull v, float& a, float& b) {
    asm("mov.b64 {%0, %1}, %2;" : "=f"(a), "=f"(b) : "l"(v));
}
__device__ __forceinline__ ull fma2(ull a, ull b, ull c) {
    ull d; asm("fma.rn.f32x2 %0, %1, %2, %3;" : "=l"(d) : "l"(a), "l"(b), "l"(c));
    return d;
}
__device__ __forceinline__ ull mul2(ull a, ull b) {
    ull d; asm("mul.rn.f32x2 %0, %1, %2;" : "=l"(d) : "l"(a), "l"(b));
    return d;
}

// ---------------------------------------------------------------------------
// Spectral norm: one power-iteration step, writes 1/sigma
// ---------------------------------------------------------------------------
__global__ void spectral_kernel(const float* __restrict__ w,
                                const float* __restrict__ u)
{
    __shared__ float sv[576];
    __shared__ float red[256];
    int tid = threadIdx.x;
    float p = 0.f;
    for (int j = tid; j < 576; j += 256) {
        float s = 0.f;
        #pragma unroll 4
        for (int o = 0; o < 128; ++o) s += w[o*576 + j] * u[o];
        sv[j] = s;
        p += s * s;
    }
    red[tid] = p; __syncthreads();
    for (int s = 128; s > 0; s >>= 1) {
        if (tid < s) red[tid] += red[tid + s];
        __syncthreads();
    }
    float vinv = 1.f / (sqrtf(red[0]) + 1e-12f);
    __syncthreads();
    float q = 0.f;
    if (tid < 128) {
        float s = 0.f;
        #pragma unroll 4
        for (int j = 0; j < 576; ++j) s += w[tid*576 + j] * sv[j];
        s *= vinv;
        q = s * s;
    }
    red[tid] = q; __syncthreads();
    for (int s = 128; s > 0; s >>= 1) {
        if (tid < s) red[tid] += red[tid + s];
        __syncthreads();
    }
    if (tid == 0) g_inv_sigma = rsqrtf(red[0]);
}

// ---------------------------------------------------------------------------
// Partial-conv mask renormalization: ratio = valid ? 9/msum : 0
// ---------------------------------------------------------------------------
__global__ void ratio_kernel(const float* __restrict__ mask)
{
    int idx = blockIdx.x * 256 + threadIdx.x;
    if (idx >= BB*HH*WW) return;
    int b = idx >> 16, rem = idx & 65535;
    int h = rem >> 8, wq = rem & 255;
    float s = 0.f;
    #pragma unroll
    for (int dh = -1; dh <= 1; ++dh) {
        int gh = h + dh;
        if ((unsigned)gh >= (unsigned)HH) continue;
        #pragma unroll
        for (int dw = -1; dw <= 1; ++dw) {
            int gw = wq + dw;
            if ((unsigned)gw >= (unsigned)WW) continue;
            s += mask[(b*HH + gh)*WW + gw];
        }
    }
    g_ratio[idx] = s > 0.f ? 9.f / fmaxf(s, 1e-8f) : 0.f;
}

// ---------------------------------------------------------------------------
// Partial conv 3x3 (spectral-normalized), f32x2 packed (2 pixels / thread)
// Block: 32 oc x (8h x 64w) tile, 256 threads, 8-channel smem chunks
// ---------------------------------------------------------------------------
__global__ __launch_bounds__(256)
void conv_kernel(const float* __restrict__ x, const float* __restrict__ mask,
                 const float* __restrict__ weight, const float* __restrict__ bias)
{
    __shared__ float sIn[8][10][66];
    __shared__ ull   sW2[8][32][9];
    __shared__ float sM[10][66];

    int tid  = threadIdx.x;
    int lane = tid & 31;
    int g    = tid >> 5;                 // oc sub-group 0..7
    int b    = blockIdx.z >> 2;
    int ocBlock = (blockIdx.z & 3) * 32;
    int h0 = blockIdx.y * 8, w0 = blockIdx.x * 64;
    float inv_sigma = g_inv_sigma;

    for (int i = tid; i < 660; i += 256) {
        int r = i / 66, cc = i % 66;
        int gh = h0 - 1 + r, gw = w0 - 1 + cc;
        float v = 0.f;
        if ((unsigned)gh < (unsigned)HH && (unsigned)gw < (unsigned)WW)
            v = mask[(b*HH + gh)*WW + gw];
        sM[r][cc] = v;
    }

    ull acc[4][8];
    #pragma unroll
    for (int o = 0; o < 4; ++o)
        #pragma unroll
        for (int r = 0; r < 8; ++r) acc[o][r] = 0ull;

    for (int ch = 0; ch < CI; ch += 8) {
        __syncthreads();
        for (int i = tid; i < 5280; i += 256) {
            int c = i / 660, j = i % 660;
            int r = j / 66, cc = j % 66;
            int gh = h0 - 1 + r, gw = w0 - 1 + cc;
            float v = 0.f;
            if ((unsigned)gh < (unsigned)HH && (unsigned)gw < (unsigned)WW)
                v = x[(((size_t)b*CI + ch + c)*HH + gh)*WW + gw] * sM[r][cc];
            sIn[c][r][cc] = v;
        }
        for (int i = tid; i < 2304; i += 256) {
            int c = i / 288, rem = i % 288;
            int oc = rem / 9, k = rem % 9;
            float wv = weight[((ocBlock + oc)*CI + ch + c)*9 + k] * inv_sigma;
            sW2[c][oc][k] = pk(wv, wv);
        }
        __syncthreads();

        #pragma unroll 2
        for (int c = 0; c < 8; ++c) {
            ull wp[4][9];
            #pragma unroll
            for (int o = 0; o < 4; ++o)
                #pragma unroll
                for (int k = 0; k < 9; ++k) wp[o][k] = sW2[c][(g<<2) + o][k];

            ull a0, a1, a2, e0, e1, e2;
            {
                float2 u = *(const float2*)&sIn[c][0][2*lane];
                float2 v = *(const float2*)&sIn[c][0][2*lane + 2];
                a0 = pk(u.x, u.y); a1 = pk(u.y, v.x); a2 = pk(v.x, v.y);
            }
            {
                float2 u = *(const float2*)&sIn[c][1][2*lane];
                float2 v = *(const float2*)&sIn[c][1][2*lane + 2];
                e0 = pk(u.x, u.y); e1 = pk(u.y, v.x); e2 = pk(v.x, v.y);
            }
            #pragma unroll
            for (int r = 0; r < 8; ++r) {
                float2 u = *(const float2*)&sIn[c][r+2][2*lane];
                float2 v = *(const float2*)&sIn[c][r+2][2*lane + 2];
                ull d0 = pk(u.x, u.y), d1 = pk(u.y, v.x), d2 = pk(v.x, v.y);
                #pragma unroll
                for (int o = 0; o < 4; ++o) {
                    ull t = acc[o][r];
                    t = fma2(a0, wp[o][0], t);
                    t = fma2(a1, wp[o][1], t);
                    t = fma2(a2, wp[o][2], t);
                    t = fma2(e0, wp[o][3], t);
                    t = fma2(e1, wp[o][4], t);
                    t = fma2(e2, wp[o][5], t);
                    t = fma2(d0, wp[o][6], t);
                    t = fma2(d1, wp[o][7], t);
                    t = fma2(d2, wp[o][8], t);
                    acc[o][r] = t;
                }
                a0 = e0; a1 = e1; a2 = e2;
                e0 = d0; e1 = d1; e2 = d2;
            }
        }
    }

    float bi[4];
    #pragma unroll
    for (int o = 0; o < 4; ++o) bi[o] = bias[ocBlock + (g<<2) + o];

    #pragma unroll
    for (int r = 0; r < 8; ++r) {
        int h = h0 + r, wq = w0 + 2*lane;
        float2 rr = *(const float2*)&g_ratio[(b*HH + h)*WW + wq];
        #pragma unroll
        for (int o = 0; o < 4; ++o) {
            int oc = ocBlock + (g<<2) + o;
            float lo, hi;
            upk(acc[o][r], lo, hi);
            float2 ov;
            ov.x = rr.x > 0.f ? lo*rr.x + bi[o] : 0.f;
            ov.y = rr.y > 0.f ? hi*rr.y + bi[o] : 0.f;
            *(float2*)&g_x[(((size_t)b*CO + oc)*HH + h)*WW + wq] = ov;
        }
    }
}

// ---------------------------------------------------------------------------
// Partial GDN: y = x / sqrt(beta + gamma @ x^2), f32x2 packed, in-place
// thread = 4 oc x 8 px (4 pairs); 64-px tiles
// ---------------------------------------------------------------------------
#define GDN_GSTRIDE 132
#define GDN_SMEM ((128*GDN_GSTRIDE + 128*64) * 4)

__global__ __launch_bounds__(256, 2)
void gdn_kernel(const float* __restrict__ gamma, const float* __restrict__ beta)
{
    extern __shared__ float sm[];
    float* sG = sm;                       // [c][o], stride 132
    float* sX = sm + 128*GDN_GSTRIDE;     // [c][pix], 64 pix

    int tid = threadIdx.x;
    for (int i = tid; i < 128*128; i += 256) {
        int o = i >> 7, c = i & 127;
        sG[c*GDN_GSTRIDE + o] = gamma[i];
    }
    __syncthreads();

    int og = tid >> 3;          // 0..31 -> 4 oc
    int pg = tid & 7;           // 0..7  -> 8 px
    int o0 = og * 4;
    float be[4];
    #pragma unroll
    for (int oi = 0; oi < 4; ++oi) be[oi] = __ldg(&beta[o0 + oi]);

    const float4* sGv = (const float4*)sG;   // row stride 33
    const float4* sXv = (const float4*)sX;   // row stride 16
    float4* sXw = (float4*)sX;

    const int nTiles = BB * HH * WW / 64;    // 8192
    for (int t = blockIdx.x; t < nTiles; t += gridDim.x) {
        int b = t >> 10;
        int base = (t & 1023) * 64;

        for (int i = tid; i < 128*16; i += 256) {
            int c = i >> 4, pv = i & 15;
            sXw[c*16 + pv] =
                ((const float4*)(g_x + ((size_t)(b*CO + c))*HH*WW + base))[pv];
        }
        __syncthreads();

        ull acc[4][4];
        #pragma unroll
        for (int oi = 0; oi < 4; ++oi)
            #pragma unroll
            for (int p = 0; p < 4; ++p) acc[oi][p] = 0ull;

        #pragma unroll 2
        for (int c = 0; c < 128; ++c) {
            float4 xa = sXv[c*16 + (pg<<1)];
            float4 xb = sXv[c*16 + (pg<<1) + 1];
            ull p0 = pk(xa.x, xa.y), p1 = pk(xa.z, xa.w);
            ull p2 = pk(xb.x, xb.y), p3 = pk(xb.z, xb.w);
            ull s0 = mul2(p0, p0), s1 = mul2(p1, p1);
            ull s2 = mul2(p2, p2), s3 = mul2(p3, p3);
            float4 gv = sGv[c*33 + og];
            ull G[4] = {pk(gv.x, gv.x), pk(gv.y, gv.y), pk(gv.z, gv.z), pk(gv.w, gv.w)};
            #pragma unroll
            for (int oi = 0; oi < 4; ++oi) {
                acc[oi][0] = fma2(G[oi], s0, acc[oi][0]);
                acc[oi][1] = fma2(G[oi], s1, acc[oi][1]);
                acc[oi][2] = fma2(G[oi], s2, acc[oi][2]);
                acc[oi][3] = fma2(G[oi], s3, acc[oi][3]);
            }
        }

        #pragma unroll
        for (int oi = 0; oi < 4; ++oi) {
            #pragma unroll
            for (int j = 0; j < 2; ++j) {
                float4 xv = sXv[(o0 + oi)*16 + (pg<<1) + j];
                float d0, d1, d2, d3;
                upk(acc[oi][2*j],     d0, d1);
                upk(acc[oi][2*j + 1], d2, d3);
                float4 yv;
                yv.x = xv.x * rsqrtf(be[oi] + d0);
                yv.y = xv.y * rsqrtf(be[oi] + d1);
                yv.z = xv.z * rsqrtf(be[oi] + d2);
                yv.w = xv.w * rsqrtf(be[oi] + d3);
                ((float4*)(g_x + ((size_t)(b*CO + o0 + oi))*HH*WW + base))[(pg<<1) + j] = yv;
            }
        }
        __syncthreads();
    }
}

// ---------------------------------------------------------------------------
// Fused 2D DWT (CDF 9/7 analysis), both separable stages in smem
// ---------------------------------------------------------------------------
__global__ __launch_bounds__(256)
void dwt_kernel(float* __restrict__ out)
{
    __shared__ float sT[40][72];
    __shared__ float sLo[16][72];
    __shared__ float sHi[16][72];

    int tid = threadIdx.x;
    int z = blockIdx.z;                       // b*128 + c
    int hb = blockIdx.y * 16, wb = blockIdx.x * 32;
    const float* src = g_x + (size_t)z * HH * WW;

    for (int i = tid; i < 40*72; i += 256) {
        int r = i / 72, cc = i % 72;
        int gr = refl(2*hb - 4 + r, HH);
        int gc = refl(2*wb - 4 + cc, WW);
        sT[r][cc] = src[gr*WW + gc];
    }
    __syncthreads();

    for (int i = tid; i < 16*72; i += 256) {
        int r = i / 72, cc = i % 72;
        float lo = 0.f, hi = 0.f;
        #pragma unroll
        for (int k = 0; k < 9; ++k) lo += c_h0[k] * sT[2*r + k][cc];
        #pragma unroll
        for (int k = 0; k < 7; ++k) hi += c_h1[k] * sT[2*r + k + 1][cc];
        sLo[r][cc] = lo;
        sHi[r][cc] = hi;
    }
    __syncthreads();

    for (int i = tid; i < 16*32; i += 256) {
        int r = i / 32, co = i % 32;
        float ll = 0.f, lh = 0.f, hl = 0.f, hh = 0.f;
        #pragma unroll
        for (int k = 0; k < 9; ++k) {
            ll += c_h0[k] * sLo[r][2*co + k];
            hl += c_h0[k] * sHi[r][2*co + k];
        }
        #pragma unroll
        for (int k = 0; k < 7; ++k) {
            lh += c_h1[k] * sLo[r][2*co + k + 1];
            hh += c_h1[k] * sHi[r][2*co + k + 1];
        }
        size_t idx = (size_t)z*16384 + (size_t)(hb + r)*128 + (wb + co);
        out[OFF_LL + idx] = ll;
        out[OFF_LH + idx] = lh;
        out[OFF_HL + idx] = hl;
        out[OFF_HH + idx] = hh;
    }
}

// ---------------------------------------------------------------------------
// Mask DWT: count>0 composition == OR over reflected 9/7 windows
// ---------------------------------------------------------------------------
__global__ void maskdwt_kernel(float* __restrict__ out)
{
    int idx = blockIdx.x * 256 + threadIdx.x;
    if (idx >= BB*128*128) return;
    int b = idx >> 14, rem = idx & 16383;
    int ho = rem >> 7, wo = rem & 127;

    bool mll = false, mlh = false, mhl = false, mhh = false;
    #pragma unroll
    for (int dr = -4; dr <= 4; ++dr) {
        int gr = refl(2*ho + dr, HH);
        bool row9 = false, row7 = false;
        #pragma unroll
        for (int dc = -4; dc <= 4; ++dc) {
            int gc = refl(2*wo + dc, WW);
            bool v = g_ratio[(b*HH + gr)*WW + gc] > 0.f;
            row9 |= v;
            if (dc >= -3 && dc <= 3) row7 |= v;
        }
        mll |= row9;
        mlh |= row7;
        if (dr >= -3 && dr <= 3) { mhl |= row9; mhh |= row7; }
    }
    out[OFF_MLL + idx] = mll ? 1.f : 0.f;
    out[OFF_MLH + idx] = mlh ? 1.f : 0.f;
    out[OFF_MHL + idx] = mhl ? 1.f : 0.f;
    out[OFF_MHH + idx] = mhh ? 1.f : 0.f;
}

// ---------------------------------------------------------------------------
extern "C" void kernel_launch(void* const* d_in, const int* in_sizes, int n_in,
                              void* d_out, int out_size)
{
    const float* tensor = (const float*)d_in[0];
    const float* mask   = (const float*)d_in[1];
    const float* weight = (const float*)d_in[2];
    const float* bias   = (const float*)d_in[3];
    const float* u      = (const float*)d_in[4];
    const float* beta   = (const float*)d_in[5];
    const float* gamma  = (const float*)d_in[6];
    float* out = (float*)d_out;

    cudaFuncSetAttribute(gdn_kernel,
                         cudaFuncAttributeMaxDynamicSharedMemorySize, GDN_SMEM);

    spectral_kernel<<<1, 256>>>(weight, u);
    ratio_kernel<<<(BB*HH*WW + 255)/256, 256>>>(mask);
    conv_kernel<<<dim3(WW/64, HH/8, BB*4), 256>>>(tensor, mask, weight, bias);
    gdn_kernel<<<296, 256, GDN_SMEM>>>(gamma, beta);
    dwt_kernel<<<dim3(4, 8, BB*CO), 256>>>(out);
    maskdwt_kernel<<<(BB*128*128 + 255)/256, 256>>>(out);
}